// round 2
// baseline (speedup 1.0000x reference)
#include <cuda_runtime.h>
#include <math.h>

// Shapes (fixed by the problem)
#define Bb   4
#define Tt   4096
#define Dm   1024
#define Kk   64
#define K2   128
#define Hh   4
#define Khd  16
#define NCH  64            // n_chunks = T / 64
#define BT   (Bb*Tt)       // 16384
#define MLP  4096
#define OUT_ELEMS (BT*Dm)  // 16777216

// ---------------- scratch (static device memory; no allocation) ----------------
__device__ float g_xn     [BT*Dm];
__device__ float g_beta_l [BT*K2];
__device__ float g_beta_a [BT*K2];
__device__ float g_hbuf   [BT*Dm];
__device__ float g_x1     [BT*Dm];
__device__ float g_xn2    [BT*Dm];
__device__ float g_hidden [BT*MLP];

// ---------------- LayerNorm: one block (256 thr) per row of 1024 ----------------
__global__ void ln_kernel(const float* __restrict__ in, float* __restrict__ out,
                          const float* __restrict__ g, const float* __restrict__ bta)
{
    int row = blockIdx.x;
    const float4* p = (const float4*)(in + (size_t)row * Dm);
    float4 v = p[threadIdx.x];
    float s  = v.x + v.y + v.z + v.w;
    float ss = v.x*v.x + v.y*v.y + v.z*v.z + v.w*v.w;
    #pragma unroll
    for (int o = 16; o > 0; o >>= 1) {
        s  += __shfl_down_sync(0xffffffffu, s,  o);
        ss += __shfl_down_sync(0xffffffffu, ss, o);
    }
    __shared__ float rs[8], rss[8];
    __shared__ float smean, srstd;
    int warp = threadIdx.x >> 5, lane = threadIdx.x & 31;
    if (lane == 0) { rs[warp] = s; rss[warp] = ss; }
    __syncthreads();
    if (threadIdx.x == 0) {
        float ts = 0.f, tss = 0.f;
        #pragma unroll
        for (int w = 0; w < 8; w++) { ts += rs[w]; tss += rss[w]; }
        float mean = ts * (1.f/Dm);
        float var  = tss * (1.f/Dm) - mean*mean;
        smean = mean;
        srstd = rsqrtf(var + 1e-5f);
    }
    __syncthreads();
    float mean = smean, rstd = srstd;
    float4 gg = ((const float4*)g)[threadIdx.x];
    float4 bb = ((const float4*)bta)[threadIdx.x];
    float4 o;
    o.x = (v.x - mean) * rstd * gg.x + bb.x;
    o.y = (v.y - mean) * rstd * gg.y + bb.y;
    o.z = (v.z - mean) * rstd * gg.z + bb.z;
    o.w = (v.w - mean) * rstd * gg.w + bb.w;
    ((float4*)(out + (size_t)row * Dm))[threadIdx.x] = o;
}

// ---------------- GEMM: C[m][n] = sum_k A[m][k]*B[n][k]  (+ epilogue) ----------------
// A: M x Kd row-major, B: N x Kd row-major. M,N multiples of 128, Kd multiple of 8.
// EPI 0: C = acc
// EPI 1: C = silu(acc + bias[n])
// EPI 2: C = aux1 + sigmoid(acc + bias[n]) * aux2
// EPI 3: C = acc + bias[n] + aux1
template<int EPI>
__global__ void __launch_bounds__(256)
gemm_kernel(const float* __restrict__ A, const float* __restrict__ Bw,
            float* __restrict__ C, int M, int N, int Kd,
            const float* __restrict__ bias,
            const float* __restrict__ aux1, const float* __restrict__ aux2)
{
    __shared__ float As[8][128];
    __shared__ float Bs[8][128];
    int tid  = threadIdx.x;
    int brow = blockIdx.y * 128;
    int bcol = blockIdx.x * 128;
    int lrow = tid >> 1;
    int lcol = (tid & 1) * 4;
    const float* Aptr = A  + (size_t)(brow + lrow) * Kd + lcol;
    const float* Bptr = Bw + (size_t)(bcol + lrow) * Kd + lcol;
    int tx = tid & 15, ty = tid >> 4;

    float acc[8][8];
    #pragma unroll
    for (int r = 0; r < 8; r++)
        #pragma unroll
        for (int c = 0; c < 8; c++) acc[r][c] = 0.f;

    float4 av = *(const float4*)Aptr;
    float4 bv = *(const float4*)Bptr;

    for (int k0 = 0; k0 < Kd; k0 += 8) {
        As[lcol+0][lrow] = av.x; As[lcol+1][lrow] = av.y;
        As[lcol+2][lrow] = av.z; As[lcol+3][lrow] = av.w;
        Bs[lcol+0][lrow] = bv.x; Bs[lcol+1][lrow] = bv.y;
        Bs[lcol+2][lrow] = bv.z; Bs[lcol+3][lrow] = bv.w;
        __syncthreads();
        if (k0 + 8 < Kd) {                    // prefetch next tile
            av = *(const float4*)(Aptr + k0 + 8);
            bv = *(const float4*)(Bptr + k0 + 8);
        }
        #pragma unroll
        for (int kk = 0; kk < 8; kk++) {
            float4 a0 = *(const float4*)&As[kk][ty*8];
            float4 a1 = *(const float4*)&As[kk][ty*8 + 4];
            float4 b0 = *(const float4*)&Bs[kk][tx*8];
            float4 b1 = *(const float4*)&Bs[kk][tx*8 + 4];
            float ar[8] = {a0.x,a0.y,a0.z,a0.w,a1.x,a1.y,a1.z,a1.w};
            float br[8] = {b0.x,b0.y,b0.z,b0.w,b1.x,b1.y,b1.z,b1.w};
            #pragma unroll
            for (int r = 0; r < 8; r++)
                #pragma unroll
                for (int c = 0; c < 8; c++)
                    acc[r][c] += ar[r] * br[c];
        }
        __syncthreads();
    }

    #pragma unroll
    for (int r = 0; r < 8; r++) {
        int row = brow + ty*8 + r;
        #pragma unroll
        for (int c = 0; c < 8; c++) {
            int col = bcol + tx*8 + c;
            size_t idx = (size_t)row * N + col;
            float v = acc[r][c];
            if (EPI == 0) {
                C[idx] = v;
            } else if (EPI == 1) {
                v += bias[col];
                C[idx] = v / (1.f + expf(-v));
            } else if (EPI == 2) {
                float gt = 1.f / (1.f + expf(-(v + bias[col])));
                C[idx] = aux1[idx] + gt * aux2[idx];
            } else { // EPI == 3
                C[idx] = v + bias[col] + aux1[idx];
            }
        }
    }
}

// ---------------- depthwise causal conv (4-tap) + bias + SiLU ----------------
__global__ void conv_silu_kernel(const float* __restrict__ beta,
                                 const float* __restrict__ w,
                                 const float* __restrict__ bias,
                                 float* __restrict__ out)
{
    int idx = blockIdx.x * blockDim.x + threadIdx.x;   // over BT*K2
    int c  = idx & 127;
    int bt = idx >> 7;
    int t  = bt & (Tt - 1);
    float acc = bias[c];
    #pragma unroll
    for (int j = 0; j < 4; j++) {
        int tt = t - 3 + j;
        if (tt >= 0)
            acc += beta[(size_t)(bt - 3 + j) * 128 + c] * w[c * 4 + j];
    }
    out[idx] = acc / (1.f + expf(-acc));               // silu
}

// ---------------- fused SSD (ANTI-CAUSAL per reference) + coupling + eig write ------
// Reference semantics (derived from the mask direction j >= i):
//   intra[i] = sum_{j>=i} lam^{j-i} * b[j]       (reverse scan within chunk)
//   prop[i]  = (i == 0) ? 1 : 0
//   out[i]   = intra[i] + (i==0) * carry ;  carry_{n+1} = out_n[63] = b_n[63]
// One block per (batch, chunk); scan done in-place in SMEM, then 16x16
// per-head coupling applied and eig (= concat(c_r, c_i)) written.
__global__ void __launch_bounds__(256)
ssd_fused_kernel(const float* __restrict__ beta_a,
                 const float* __restrict__ log_decay,
                 const float* __restrict__ freq,
                 const float* __restrict__ coupling,
                 float* __restrict__ eig)
{
    __shared__ float sb[64 * 128];       // chunk tile: 64 pos x (64 real | 64 imag)
    __shared__ float scoup[Hh * Khd * Khd];
    int b  = blockIdx.x >> 6;
    int ch = blockIdx.x & 63;
    size_t base = (size_t)(b * Tt + ch * 64) * 128;
    const float4* src = (const float4*)(beta_a + base);
    for (int i = threadIdx.x; i < 64 * 128 / 4; i += 256)
        ((float4*)sb)[i] = src[i];
    for (int i = threadIdx.x; i < Hh * Khd * Khd; i += 256)
        scoup[i] = coupling[i];
    __syncthreads();

    if (threadIdx.x < 64) {
        int k = threadIdx.x;
        float mag = 1.f / (1.f + expf(-log_decay[k]));
        float f   = freq[k];
        float lr = mag * cosf(f), li = mag * sinf(f);
        float zr = 0.f, zi = 0.f;
        // reverse scan, in place: z_i = lam * z_{i+1} + b[i]
        for (int i = 63; i >= 0; i--) {
            float br = sb[i * 128 + k];
            float bi = sb[i * 128 + 64 + k];
            float nr = lr * zr - li * zi + br;
            float ni = lr * zi + li * zr + bi;
            zr = nr; zi = ni;
            sb[i * 128 + k]      = zr;
            sb[i * 128 + 64 + k] = zi;
        }
        // carry from previous chunk: out[0] += b_prev[63]  (zero for chunk 0)
        if (ch > 0) {
            sb[k]      += beta_a[base - 128 + k];
            sb[64 + k] += beta_a[base - 128 + 64 + k];
        }
    }
    __syncthreads();

    // per-head coupling: eig[.., h*16+j] = sum_kk coup[h,j,kk] * c[.., h*16+kk]
    for (int task = threadIdx.x; task < 64 * 64; task += 256) {
        int i  = task >> 6;       // position within chunk
        int ko = task & 63;       // output channel
        int h = ko >> 4, j = ko & 15;
        const float* cw = scoup + h * (Khd * Khd) + j * Khd;
        const float* rowr = sb + i * 128 + h * Khd;
        const float* rowi = rowr + 64;
        float or_ = 0.f, oi_ = 0.f;
        #pragma unroll
        for (int kk = 0; kk < Khd; kk++) {
            float w = cw[kk];
            or_ += w * rowr[kk];
            oi_ += w * rowi[kk];
        }
        size_t e = (size_t)(b * Tt + ch * 64 + i) * 128;
        eig[e + ko]      = or_;
        eig[e + 64 + ko] = oi_;
    }
}

// ---------------- launcher ----------------
extern "C" void kernel_launch(void* const* d_in, const int* in_sizes, int n_in,
                              void* d_out, int out_size)
{
    const float* x          = (const float*)d_in[0];
    const float* in_proj_w  = (const float*)d_in[1];
    const float* conv_w     = (const float*)d_in[2];
    const float* conv_b     = (const float*)d_in[3];
    const float* log_decay  = (const float*)d_in[4];
    const float* frequency  = (const float*)d_in[5];
    const float* coupling   = (const float*)d_in[6];
    const float* out_proj_w = (const float*)d_in[7];
    const float* gate_w     = (const float*)d_in[8];
    const float* gate_b     = (const float*)d_in[9];
    const float* mlp_w1     = (const float*)d_in[10];
    const float* mlp_b1     = (const float*)d_in[11];
    const float* mlp_w2     = (const float*)d_in[12];
    const float* mlp_b2     = (const float*)d_in[13];
    const float* ln1_g      = (const float*)d_in[14];
    const float* ln1_b      = (const float*)d_in[15];
    const float* ln2_g      = (const float*)d_in[16];
    const float* ln2_b      = (const float*)d_in[17];

    float* out = (float*)d_out;
    float* eig = out + OUT_ELEMS;

    float *xn, *beta_l, *beta_a, *hb, *x1, *xn2, *hidden;
    cudaGetSymbolAddress((void**)&xn,     g_xn);
    cudaGetSymbolAddress((void**)&beta_l, g_beta_l);
    cudaGetSymbolAddress((void**)&beta_a, g_beta_a);
    cudaGetSymbolAddress((void**)&hb,     g_hbuf);
    cudaGetSymbolAddress((void**)&x1,     g_x1);
    cudaGetSymbolAddress((void**)&xn2,    g_xn2);
    cudaGetSymbolAddress((void**)&hidden, g_hidden);

    // 1. xn = LN1(x)
    ln_kernel<<<BT, 256>>>(x, xn, ln1_g, ln1_b);
    // 2. beta_lin = xn @ in_proj_w.T   (16384 x 128, K=1024)
    gemm_kernel<0><<<dim3(1, 128), 256>>>(xn, in_proj_w, beta_l, BT, 128, 1024,
                                          nullptr, nullptr, nullptr);
    // 3. beta = silu(causal depthwise conv + bias)
    conv_silu_kernel<<<(BT * K2) / 256, 256>>>(beta_l, conv_w, conv_b, beta_a);
    // 4. SSD (anti-causal reverse scan + carry + coupling) -> eig
    ssd_fused_kernel<<<Bb * NCH, 256>>>(beta_a, log_decay, frequency, coupling, eig);
    // 5. h = eig @ out_proj_w.T  (16384 x 1024, K=128)
    gemm_kernel<0><<<dim3(8, 128), 256>>>(eig, out_proj_w, hb, BT, 1024, 128,
                                          nullptr, nullptr, nullptr);
    // 6. x1 = x + sigmoid(xn @ gate_w.T + gate_b) * h   (fused epilogue)
    gemm_kernel<2><<<dim3(8, 128), 256>>>(xn, gate_w, x1, BT, 1024, 1024,
                                          gate_b, x, hb);
    // 7. xn2 = LN2(x1)
    ln_kernel<<<BT, 256>>>(x1, xn2, ln2_g, ln2_b);
    // 8. hidden = silu(xn2 @ mlp_w1.T + b1)
    gemm_kernel<1><<<dim3(32, 128), 256>>>(xn2, mlp_w1, hidden, BT, 4096, 1024,
                                           mlp_b1, nullptr, nullptr);
    // 9. out = x1 + hidden @ mlp_w2.T + b2
    gemm_kernel<3><<<dim3(8, 128), 256>>>(hidden, mlp_w2, out, BT, 1024, 4096,
                                          mlp_b2, x1, nullptr);
}

// round 3
// speedup vs baseline: 2.3869x; 2.3869x over previous
#include <cuda_runtime.h>
#include <math.h>

// Shapes (fixed by the problem)
#define Bb   4
#define Tt   4096
#define Dm   1024
#define Kk   64
#define K2   128
#define Hh   4
#define Khd  16
#define NCH  64
#define BT   (Bb*Tt)       // 16384
#define MLP  4096
#define OUT_ELEMS (BT*Dm)  // 16777216

// ---------------- scratch (static device memory; no allocation) ----------------
__device__ float g_xn     [BT*Dm];
__device__ float g_beta_l [BT*K2];
__device__ float g_beta_a [BT*K2];
__device__ float g_hbuf   [BT*Dm];
__device__ float g_x1     [BT*Dm];
__device__ float g_xn2    [BT*Dm];
__device__ float g_hidden [BT*MLP];

// ---------------- helpers ----------------
__device__ __forceinline__ unsigned f2tf(float f) {
    unsigned u;
    asm("cvt.rna.tf32.f32 %0, %1;" : "=r"(u) : "f"(f));
    return u;
}

// ---------------- LayerNorm: one block (256 thr) per row of 1024 ----------------
__global__ void ln_kernel(const float* __restrict__ in, float* __restrict__ out,
                          const float* __restrict__ g, const float* __restrict__ bta)
{
    int row = blockIdx.x;
    const float4* p = (const float4*)(in + (size_t)row * Dm);
    float4 v = p[threadIdx.x];
    float s  = v.x + v.y + v.z + v.w;
    float ss = v.x*v.x + v.y*v.y + v.z*v.z + v.w*v.w;
    #pragma unroll
    for (int o = 16; o > 0; o >>= 1) {
        s  += __shfl_down_sync(0xffffffffu, s,  o);
        ss += __shfl_down_sync(0xffffffffu, ss, o);
    }
    __shared__ float rs[8], rss[8];
    __shared__ float smean, srstd;
    int warp = threadIdx.x >> 5, lane = threadIdx.x & 31;
    if (lane == 0) { rs[warp] = s; rss[warp] = ss; }
    __syncthreads();
    if (threadIdx.x == 0) {
        float ts = 0.f, tss = 0.f;
        #pragma unroll
        for (int w = 0; w < 8; w++) { ts += rs[w]; tss += rss[w]; }
        float mean = ts * (1.f/Dm);
        float var  = tss * (1.f/Dm) - mean*mean;
        smean = mean;
        srstd = rsqrtf(var + 1e-5f);
    }
    __syncthreads();
    float mean = smean, rstd = srstd;
    float4 gg = ((const float4*)g)[threadIdx.x];
    float4 bb = ((const float4*)bta)[threadIdx.x];
    float4 o;
    o.x = (v.x - mean) * rstd * gg.x + bb.x;
    o.y = (v.y - mean) * rstd * gg.y + bb.y;
    o.z = (v.z - mean) * rstd * gg.z + bb.z;
    o.w = (v.w - mean) * rstd * gg.w + bb.w;
    ((float4*)(out + (size_t)row * Dm))[threadIdx.x] = o;
}

// ---------------- fp32 SIMT GEMM (kept for in_proj / out_proj, exact path) -------
// C[m][n] = sum_k A[m][k]*B[n][k]
__global__ void __launch_bounds__(256)
gemm_kernel(const float* __restrict__ A, const float* __restrict__ Bw,
            float* __restrict__ C, int M, int N, int Kd)
{
    __shared__ float As[8][128];
    __shared__ float Bs[8][128];
    int tid  = threadIdx.x;
    int brow = blockIdx.y * 128;
    int bcol = blockIdx.x * 128;
    int lrow = tid >> 1;
    int lcol = (tid & 1) * 4;
    const float* Aptr = A  + (size_t)(brow + lrow) * Kd + lcol;
    const float* Bptr = Bw + (size_t)(bcol + lrow) * Kd + lcol;
    int tx = tid & 15, ty = tid >> 4;

    float acc[8][8];
    #pragma unroll
    for (int r = 0; r < 8; r++)
        #pragma unroll
        for (int c = 0; c < 8; c++) acc[r][c] = 0.f;

    float4 av = *(const float4*)Aptr;
    float4 bv = *(const float4*)Bptr;

    for (int k0 = 0; k0 < Kd; k0 += 8) {
        As[lcol+0][lrow] = av.x; As[lcol+1][lrow] = av.y;
        As[lcol+2][lrow] = av.z; As[lcol+3][lrow] = av.w;
        Bs[lcol+0][lrow] = bv.x; Bs[lcol+1][lrow] = bv.y;
        Bs[lcol+2][lrow] = bv.z; Bs[lcol+3][lrow] = bv.w;
        __syncthreads();
        if (k0 + 8 < Kd) {
            av = *(const float4*)(Aptr + k0 + 8);
            bv = *(const float4*)(Bptr + k0 + 8);
        }
        #pragma unroll
        for (int kk = 0; kk < 8; kk++) {
            float4 a0 = *(const float4*)&As[kk][ty*8];
            float4 a1 = *(const float4*)&As[kk][ty*8 + 4];
            float4 b0 = *(const float4*)&Bs[kk][tx*8];
            float4 b1 = *(const float4*)&Bs[kk][tx*8 + 4];
            float ar[8] = {a0.x,a0.y,a0.z,a0.w,a1.x,a1.y,a1.z,a1.w};
            float br[8] = {b0.x,b0.y,b0.z,b0.w,b1.x,b1.y,b1.z,b1.w};
            #pragma unroll
            for (int r = 0; r < 8; r++)
                #pragma unroll
                for (int c = 0; c < 8; c++)
                    acc[r][c] += ar[r] * br[c];
        }
        __syncthreads();
    }

    #pragma unroll
    for (int r = 0; r < 8; r++) {
        int row = brow + ty*8 + r;
        #pragma unroll
        for (int c = 0; c < 8; c++) {
            int col = bcol + tx*8 + c;
            C[(size_t)row * N + col] = acc[r][c];
        }
    }
}

// ---------------- tf32 tensor-core GEMM (+ epilogue) ----------------
// C[m][n] = sum_k A[m][k]*B[n][k]; A: MxKd, B: NxKd row-major, Kd % 32 == 0.
// Block tile 128x128, 8 warps (2 row x 4 col), warp tile 64x32, mma m16n8k8.
// EPI 1: C = silu(acc + bias[n])
// EPI 2: C = aux1 + sigmoid(acc + bias[n]) * aux2
// EPI 3: C = acc + bias[n] + aux1
template<int EPI>
__global__ void __launch_bounds__(256)
gemm_tf32_kernel(const float* __restrict__ A, const float* __restrict__ Bw,
                 float* __restrict__ C, int M, int N, int Kd,
                 const float* __restrict__ bias,
                 const float* __restrict__ aux1, const float* __restrict__ aux2)
{
    __shared__ unsigned As[128][36];   // padded: conflict-free frag loads
    __shared__ unsigned Bs[128][36];
    const int tid  = threadIdx.x;
    const int warp = tid >> 5, lane = tid & 31;
    const int wr = warp >> 2;          // 0..1
    const int wc = warp & 3;           // 0..3
    const int brow = blockIdx.y * 128, bcol = blockIdx.x * 128;

    // global loaders: each thread covers 16 floats of a 128x32 tile (A and B)
    const int lrow = tid >> 1;         // 0..127
    const int lcb  = (tid & 1) * 16;   // 0 or 16
    const float* Aptr = A  + (size_t)(brow + lrow) * Kd + lcb;
    const float* Bptr = Bw + (size_t)(bcol + lrow) * Kd + lcb;

    float acc[4][4][4];
    #pragma unroll
    for (int m = 0; m < 4; m++)
        #pragma unroll
        for (int n = 0; n < 4; n++)
            #pragma unroll
            for (int i = 0; i < 4; i++) acc[m][n][i] = 0.f;

    float4 av[4], bv[4];
    #pragma unroll
    for (int i = 0; i < 4; i++) {
        av[i] = *(const float4*)(Aptr + i*4);
        bv[i] = *(const float4*)(Bptr + i*4);
    }

    for (int k0 = 0; k0 < Kd; k0 += 32) {
        #pragma unroll
        for (int i = 0; i < 4; i++) {
            uint4 ua = make_uint4(f2tf(av[i].x), f2tf(av[i].y), f2tf(av[i].z), f2tf(av[i].w));
            uint4 ub = make_uint4(f2tf(bv[i].x), f2tf(bv[i].y), f2tf(bv[i].z), f2tf(bv[i].w));
            *(uint4*)&As[lrow][lcb + i*4] = ua;
            *(uint4*)&Bs[lrow][lcb + i*4] = ub;
        }
        __syncthreads();
        if (k0 + 32 < Kd) {
            #pragma unroll
            for (int i = 0; i < 4; i++) {
                av[i] = *(const float4*)(Aptr + k0 + 32 + i*4);
                bv[i] = *(const float4*)(Bptr + k0 + 32 + i*4);
            }
        }
        #pragma unroll
        for (int ks = 0; ks < 4; ks++) {
            const int kb = ks * 8;
            const int ra = lane >> 2;
            const int ca = kb + (lane & 3);
            unsigned af[4][4], bf[4][2];
            #pragma unroll
            for (int mt = 0; mt < 4; mt++) {
                int r = wr*64 + mt*16 + ra;
                af[mt][0] = As[r  ][ca  ];
                af[mt][1] = As[r+8][ca  ];
                af[mt][2] = As[r  ][ca+4];
                af[mt][3] = As[r+8][ca+4];
            }
            #pragma unroll
            for (int nt = 0; nt < 4; nt++) {
                int n = wc*32 + nt*8 + ra;
                bf[nt][0] = Bs[n][ca  ];
                bf[nt][1] = Bs[n][ca+4];
            }
            #pragma unroll
            for (int mt = 0; mt < 4; mt++)
                #pragma unroll
                for (int nt = 0; nt < 4; nt++)
                    asm volatile(
                        "mma.sync.aligned.m16n8k8.row.col.f32.tf32.tf32.f32 "
                        "{%0,%1,%2,%3}, {%4,%5,%6,%7}, {%8,%9}, {%0,%1,%2,%3};"
                        : "+f"(acc[mt][nt][0]), "+f"(acc[mt][nt][1]),
                          "+f"(acc[mt][nt][2]), "+f"(acc[mt][nt][3])
                        : "r"(af[mt][0]), "r"(af[mt][1]), "r"(af[mt][2]), "r"(af[mt][3]),
                          "r"(bf[nt][0]), "r"(bf[nt][1]));
        }
        __syncthreads();
    }

    // epilogue: thread owns (row, col..col+1) pairs
    #pragma unroll
    for (int mt = 0; mt < 4; mt++) {
        #pragma unroll
        for (int half = 0; half < 2; half++) {
            int row = brow + wr*64 + mt*16 + (lane >> 2) + half*8;
            #pragma unroll
            for (int nt = 0; nt < 4; nt++) {
                int col = bcol + wc*32 + nt*8 + (lane & 3)*2;
                size_t idx = (size_t)row * N + col;
                float v0 = acc[mt][nt][half*2 + 0];
                float v1 = acc[mt][nt][half*2 + 1];
                float2 o;
                if (EPI == 1) {
                    v0 += bias[col]; v1 += bias[col+1];
                    o.x = v0 / (1.f + expf(-v0));
                    o.y = v1 / (1.f + expf(-v1));
                } else if (EPI == 2) {
                    float g0 = 1.f / (1.f + expf(-(v0 + bias[col])));
                    float g1 = 1.f / (1.f + expf(-(v1 + bias[col+1])));
                    float2 a1v = *(const float2*)(aux1 + idx);
                    float2 a2v = *(const float2*)(aux2 + idx);
                    o.x = a1v.x + g0 * a2v.x;
                    o.y = a1v.y + g1 * a2v.y;
                } else { // EPI == 3
                    float2 a1v = *(const float2*)(aux1 + idx);
                    o.x = v0 + bias[col]   + a1v.x;
                    o.y = v1 + bias[col+1] + a1v.y;
                }
                *(float2*)(C + idx) = o;
            }
        }
    }
}

// ---------------- depthwise causal conv (4-tap) + bias + SiLU ----------------
__global__ void conv_silu_kernel(const float* __restrict__ beta,
                                 const float* __restrict__ w,
                                 const float* __restrict__ bias,
                                 float* __restrict__ out)
{
    int idx = blockIdx.x * blockDim.x + threadIdx.x;   // over BT*K2
    int c  = idx & 127;
    int bt = idx >> 7;
    int t  = bt & (Tt - 1);
    float acc = bias[c];
    #pragma unroll
    for (int j = 0; j < 4; j++) {
        int tt = t - 3 + j;
        if (tt >= 0)
            acc += beta[(size_t)(bt - 3 + j) * 128 + c] * w[c * 4 + j];
    }
    out[idx] = acc / (1.f + expf(-acc));               // silu
}

// ---------------- fused SSD (anti-causal reverse scan) + coupling + eig --------
__global__ void __launch_bounds__(256)
ssd_fused_kernel(const float* __restrict__ beta_a,
                 const float* __restrict__ log_decay,
                 const float* __restrict__ freq,
                 const float* __restrict__ coupling,
                 float* __restrict__ eig)
{
    __shared__ float sb[64 * 128];
    __shared__ float scoup[Hh * Khd * Khd];
    int b  = blockIdx.x >> 6;
    int ch = blockIdx.x & 63;
    size_t base = (size_t)(b * Tt + ch * 64) * 128;
    const float4* src = (const float4*)(beta_a + base);
    for (int i = threadIdx.x; i < 64 * 128 / 4; i += 256)
        ((float4*)sb)[i] = src[i];
    for (int i = threadIdx.x; i < Hh * Khd * Khd; i += 256)
        scoup[i] = coupling[i];
    __syncthreads();

    if (threadIdx.x < 64) {
        int k = threadIdx.x;
        float mag = 1.f / (1.f + expf(-log_decay[k]));
        float f   = freq[k];
        float lr = mag * cosf(f), li = mag * sinf(f);
        float zr = 0.f, zi = 0.f;
        for (int i = 63; i >= 0; i--) {
            float br = sb[i * 128 + k];
            float bi = sb[i * 128 + 64 + k];
            float nr = lr * zr - li * zi + br;
            float ni = lr * zi + li * zr + bi;
            zr = nr; zi = ni;
            sb[i * 128 + k]      = zr;
            sb[i * 128 + 64 + k] = zi;
        }
        if (ch > 0) {
            sb[k]      += beta_a[base - 128 + k];
            sb[64 + k] += beta_a[base - 128 + 64 + k];
        }
    }
    __syncthreads();

    for (int task = threadIdx.x; task < 64 * 64; task += 256) {
        int i  = task >> 6;
        int ko = task & 63;
        int h = ko >> 4, j = ko & 15;
        const float* cw = scoup + h * (Khd * Khd) + j * Khd;
        const float* rowr = sb + i * 128 + h * Khd;
        const float* rowi = rowr + 64;
        float or_ = 0.f, oi_ = 0.f;
        #pragma unroll
        for (int kk = 0; kk < Khd; kk++) {
            float w = cw[kk];
            or_ += w * rowr[kk];
            oi_ += w * rowi[kk];
        }
        size_t e = (size_t)(b * Tt + ch * 64 + i) * 128;
        eig[e + ko]      = or_;
        eig[e + 64 + ko] = oi_;
    }
}

// ---------------- launcher ----------------
extern "C" void kernel_launch(void* const* d_in, const int* in_sizes, int n_in,
                              void* d_out, int out_size)
{
    const float* x          = (const float*)d_in[0];
    const float* in_proj_w  = (const float*)d_in[1];
    const float* conv_w     = (const float*)d_in[2];
    const float* conv_b     = (const float*)d_in[3];
    const float* log_decay  = (const float*)d_in[4];
    const float* frequency  = (const float*)d_in[5];
    const float* coupling   = (const float*)d_in[6];
    const float* out_proj_w = (const float*)d_in[7];
    const float* gate_w     = (const float*)d_in[8];
    const float* gate_b     = (const float*)d_in[9];
    const float* mlp_w1     = (const float*)d_in[10];
    const float* mlp_b1     = (const float*)d_in[11];
    const float* mlp_w2     = (const float*)d_in[12];
    const float* mlp_b2     = (const float*)d_in[13];
    const float* ln1_g      = (const float*)d_in[14];
    const float* ln1_b      = (const float*)d_in[15];
    const float* ln2_g      = (const float*)d_in[16];
    const float* ln2_b      = (const float*)d_in[17];

    float* out = (float*)d_out;
    float* eig = out + OUT_ELEMS;

    float *xn, *beta_l, *beta_a, *hb, *x1, *xn2, *hidden;
    cudaGetSymbolAddress((void**)&xn,     g_xn);
    cudaGetSymbolAddress((void**)&beta_l, g_beta_l);
    cudaGetSymbolAddress((void**)&beta_a, g_beta_a);
    cudaGetSymbolAddress((void**)&hb,     g_hbuf);
    cudaGetSymbolAddress((void**)&x1,     g_x1);
    cudaGetSymbolAddress((void**)&xn2,    g_xn2);
    cudaGetSymbolAddress((void**)&hidden, g_hidden);

    // 1. xn = LN1(x)
    ln_kernel<<<BT, 256>>>(x, xn, ln1_g, ln1_b);
    // 2. beta_lin = xn @ in_proj_w.T   (fp32: feeds eig, keep exact)
    gemm_kernel<<<dim3(1, 128), 256>>>(xn, in_proj_w, beta_l, BT, 128, 1024);
    // 3. beta = silu(causal depthwise conv + bias)
    conv_silu_kernel<<<(BT * K2) / 256, 256>>>(beta_l, conv_w, conv_b, beta_a);
    // 4. SSD (anti-causal reverse scan + carry + coupling) -> eig
    ssd_fused_kernel<<<Bb * NCH, 256>>>(beta_a, log_decay, frequency, coupling, eig);
    // 5. h = eig @ out_proj_w.T  (fp32)
    gemm_kernel<<<dim3(8, 128), 256>>>(eig, out_proj_w, hb, BT, 1024, 128);
    // 6. x1 = x + sigmoid(xn @ gate_w.T + gate_b) * h   (tf32 + fused epilogue)
    gemm_tf32_kernel<2><<<dim3(8, 128), 256>>>(xn, gate_w, x1, BT, 1024, 1024,
                                               gate_b, x, hb);
    // 7. xn2 = LN2(x1)
    ln_kernel<<<BT, 256>>>(x1, xn2, ln2_g, ln2_b);
    // 8. hidden = silu(xn2 @ mlp_w1.T + b1)   (tf32)
    gemm_tf32_kernel<1><<<dim3(32, 128), 256>>>(xn2, mlp_w1, hidden, BT, 4096, 1024,
                                                mlp_b1, nullptr, nullptr);
    // 9. out = x1 + hidden @ mlp_w2.T + b2    (tf32)
    gemm_tf32_kernel<3><<<dim3(8, 128), 256>>>(hidden, mlp_w2, out, BT, 1024, 4096,
                                               mlp_b2, x1, nullptr);
}

// round 5
// speedup vs baseline: 2.9456x; 1.2341x over previous
#include <cuda_runtime.h>
#include <math.h>

// Shapes (fixed by the problem)
#define Bb   4
#define Tt   4096
#define Dm   1024
#define Kk   64
#define K2   128
#define Hh   4
#define Khd  16
#define NCH  64
#define BT   (Bb*Tt)       // 16384
#define MLP  4096
#define OUT_ELEMS (BT*Dm)  // 16777216

#define STAGES 3
#define SMEM_BYTES (STAGES * 2 * 128 * 32 * 4)   // 98304

// ---------------- scratch (static device memory; no allocation) ----------------
__device__ float g_xn     [BT*Dm];
__device__ float g_beta_l [BT*K2];
__device__ float g_beta_a [BT*K2];
__device__ float g_hbuf   [BT*Dm];
__device__ float g_x1     [BT*Dm];
__device__ float g_xn2    [BT*Dm];
__device__ float g_hidden [BT*MLP];
// tf32-rounded weight copies
__device__ float g_w_in   [K2*Dm];
__device__ float g_w_out  [Dm*K2];
__device__ float g_w_gate [Dm*Dm];
__device__ float g_w_m1   [MLP*Dm];
__device__ float g_w_m2   [Dm*MLP];

// ---------------- helpers ----------------
__device__ __forceinline__ unsigned f2tf(float f) {
    unsigned u;
    asm("cvt.rna.tf32.f32 %0, %1;" : "=r"(u) : "f"(f));
    return u;
}
__device__ __forceinline__ float roundtf(float f) { return __uint_as_float(f2tf(f)); }

__device__ __forceinline__ void cp_async16(void* smem_dst, const void* gptr) {
    unsigned saddr = (unsigned)__cvta_generic_to_shared(smem_dst);
    asm volatile("cp.async.cg.shared.global [%0], [%1], 16;\n" :: "r"(saddr), "l"(gptr));
}
__device__ __forceinline__ void cp_commit() { asm volatile("cp.async.commit_group;\n"); }
__device__ __forceinline__ void cp_wait1()  { asm volatile("cp.async.wait_group 1;\n"); }

// swizzled word index within a 128x32 tile (conflict-free frag loads, no padding)
__device__ __forceinline__ int swz(int r, int c) {
    return r * 32 + ((((c >> 2) ^ r) & 7) << 2) + (c & 3);
}

// ---------------- weight rounding ----------------
__global__ void round_tf32_kernel(const float* __restrict__ in, float* __restrict__ out, int n)
{
    int i = blockIdx.x * blockDim.x + threadIdx.x;
    if (i < n) out[i] = roundtf(in[i]);
}

// ---------------- LayerNorm (writes tf32-rounded output) ----------------
__global__ void ln_kernel(const float* __restrict__ in, float* __restrict__ out,
                          const float* __restrict__ g, const float* __restrict__ bta)
{
    int row = blockIdx.x;
    const float4* p = (const float4*)(in + (size_t)row * Dm);
    float4 v = p[threadIdx.x];
    float s  = v.x + v.y + v.z + v.w;
    float ss = v.x*v.x + v.y*v.y + v.z*v.z + v.w*v.w;
    #pragma unroll
    for (int o = 16; o > 0; o >>= 1) {
        s  += __shfl_down_sync(0xffffffffu, s,  o);
        ss += __shfl_down_sync(0xffffffffu, ss, o);
    }
    __shared__ float rs[8], rss[8];
    __shared__ float smean, srstd;
    int warp = threadIdx.x >> 5, lane = threadIdx.x & 31;
    if (lane == 0) { rs[warp] = s; rss[warp] = ss; }
    __syncthreads();
    if (threadIdx.x == 0) {
        float ts = 0.f, tss = 0.f;
        #pragma unroll
        for (int w = 0; w < 8; w++) { ts += rs[w]; tss += rss[w]; }
        float mean = ts * (1.f/Dm);
        float var  = tss * (1.f/Dm) - mean*mean;
        smean = mean;
        srstd = rsqrtf(var + 1e-5f);
    }
    __syncthreads();
    float mean = smean, rstd = srstd;
    float4 gg = ((const float4*)g)[threadIdx.x];
    float4 bb = ((const float4*)bta)[threadIdx.x];
    float4 o;
    o.x = roundtf((v.x - mean) * rstd * gg.x + bb.x);
    o.y = roundtf((v.y - mean) * rstd * gg.y + bb.y);
    o.z = roundtf((v.z - mean) * rstd * gg.z + bb.z);
    o.w = roundtf((v.w - mean) * rstd * gg.w + bb.w);
    ((float4*)(out + (size_t)row * Dm))[threadIdx.x] = o;
}

// ---------------- tf32 tensor GEMM, 3-stage cp.async pipeline ----------------
// C[m][n] = sum_k A[m][k]*B[n][k]; A,B already tf32-rounded. Kd % 32 == 0.
// Block 128x128, 8 warps (2x4), warp tile 64x32, mma m16n8k8.
// EPI 0: C = acc
// EPI 1: C = roundtf(silu(acc + bias[n]))
// EPI 2: C = aux1 + sigmoid(acc + bias[n]) * aux2
// EPI 3: C = acc + bias[n] + aux1
template<int EPI>
__global__ void __launch_bounds__(256)
gemm_tf32_kernel(const float* __restrict__ A, const float* __restrict__ Bw,
                 float* __restrict__ C, int M, int N, int Kd,
                 const float* __restrict__ bias,
                 const float* __restrict__ aux1, const float* __restrict__ aux2)
{
    extern __shared__ float dsm[];
    float* As = dsm;                        // STAGES tiles of 128x32
    float* Bs = dsm + STAGES * 128 * 32;

    const int tid  = threadIdx.x;
    const int warp = tid >> 5, lane = tid & 31;
    const int wr = warp >> 2;               // 0..1
    const int wc = warp & 3;                // 0..3
    const int brow = blockIdx.y * 128, bcol = blockIdx.x * 128;

    // loader mapping: row = tid>>1, chunk base = (tid&1)*4 (each chunk = 4 floats)
    const int lr  = tid >> 1;
    const int lcb = (tid & 1) * 4;
    const float* Arow = A  + (size_t)(brow + lr) * Kd;
    const float* Brow = Bw + (size_t)(bcol + lr) * Kd;

    const int KT = Kd >> 5;                 // k-chunks of 32

    // issue one stage's loads
    auto issue = [&](int buf, int k0) {
        float* Atile = As + buf * (128 * 32);
        float* Btile = Bs + buf * (128 * 32);
        #pragma unroll
        for (int i = 0; i < 4; i++) {
            int cc = lcb + i;
            int dst = lr * 32 + (((cc ^ lr) & 7) << 2);
            cp_async16(Atile + dst, Arow + k0 + cc * 4);
            cp_async16(Btile + dst, Brow + k0 + cc * 4);
        }
    };

    float acc[4][4][4];
    #pragma unroll
    for (int m = 0; m < 4; m++)
        #pragma unroll
        for (int n = 0; n < 4; n++)
            #pragma unroll
            for (int i = 0; i < 4; i++) acc[m][n][i] = 0.f;

    // prologue: stages 0,1
    issue(0, 0);  cp_commit();
    issue(1, 32); cp_commit();

    const int ra = lane >> 2;
    const int c0 = lane & 3;

    for (int kt = 0; kt < KT; kt++) {
        cp_wait1();
        __syncthreads();
        if (kt + 2 < KT) issue((kt + 2) % STAGES, (kt + 2) * 32);
        cp_commit();

        const float* Atile = As + (kt % STAGES) * (128 * 32);
        const float* Btile = Bs + (kt % STAGES) * (128 * 32);

        #pragma unroll
        for (int ks = 0; ks < 4; ks++) {
            const int ca = ks * 8 + c0;
            unsigned af[4][4], bf[4][2];
            #pragma unroll
            for (int mt = 0; mt < 4; mt++) {
                int r = wr*64 + mt*16 + ra;
                af[mt][0] = __float_as_uint(Atile[swz(r,     ca    )]);
                af[mt][1] = __float_as_uint(Atile[swz(r + 8, ca    )]);
                af[mt][2] = __float_as_uint(Atile[swz(r,     ca + 4)]);
                af[mt][3] = __float_as_uint(Atile[swz(r + 8, ca + 4)]);
            }
            #pragma unroll
            for (int nt = 0; nt < 4; nt++) {
                int n = wc*32 + nt*8 + ra;
                bf[nt][0] = __float_as_uint(Btile[swz(n, ca    )]);
                bf[nt][1] = __float_as_uint(Btile[swz(n, ca + 4)]);
            }
            #pragma unroll
            for (int mt = 0; mt < 4; mt++)
                #pragma unroll
                for (int nt = 0; nt < 4; nt++)
                    asm volatile(
                        "mma.sync.aligned.m16n8k8.row.col.f32.tf32.tf32.f32 "
                        "{%0,%1,%2,%3}, {%4,%5,%6,%7}, {%8,%9}, {%0,%1,%2,%3};"
                        : "+f"(acc[mt][nt][0]), "+f"(acc[mt][nt][1]),
                          "+f"(acc[mt][nt][2]), "+f"(acc[mt][nt][3])
                        : "r"(af[mt][0]), "r"(af[mt][1]), "r"(af[mt][2]), "r"(af[mt][3]),
                          "r"(bf[nt][0]), "r"(bf[nt][1]));
        }
        __syncthreads();
    }

    // epilogue: thread owns (row, col..col+1) pairs
    #pragma unroll
    for (int mt = 0; mt < 4; mt++) {
        #pragma unroll
        for (int half = 0; half < 2; half++) {
            int row = brow + wr*64 + mt*16 + ra + half*8;
            #pragma unroll
            for (int nt = 0; nt < 4; nt++) {
                int col = bcol + wc*32 + nt*8 + c0*2;
                size_t idx = (size_t)row * N + col;
                float v0 = acc[mt][nt][half*2 + 0];
                float v1 = acc[mt][nt][half*2 + 1];
                float2 o;
                if (EPI == 0) {
                    o.x = v0; o.y = v1;
                } else if (EPI == 1) {
                    v0 += bias[col]; v1 += bias[col+1];
                    o.x = roundtf(v0 / (1.f + expf(-v0)));
                    o.y = roundtf(v1 / (1.f + expf(-v1)));
                } else if (EPI == 2) {
                    float g0 = 1.f / (1.f + expf(-(v0 + bias[col])));
                    float g1 = 1.f / (1.f + expf(-(v1 + bias[col+1])));
                    float2 a1v = *(const float2*)(aux1 + idx);
                    float2 a2v = *(const float2*)(aux2 + idx);
                    o.x = a1v.x + g0 * a2v.x;
                    o.y = a1v.y + g1 * a2v.y;
                } else { // EPI == 3
                    float2 a1v = *(const float2*)(aux1 + idx);
                    o.x = v0 + bias[col]   + a1v.x;
                    o.y = v1 + bias[col+1] + a1v.y;
                }
                *(float2*)(C + idx) = o;
            }
        }
    }
}

// ---------------- depthwise causal conv (4-tap) + bias + SiLU ----------------
__global__ void conv_silu_kernel(const float* __restrict__ beta,
                                 const float* __restrict__ w,
                                 const float* __restrict__ bias,
                                 float* __restrict__ out)
{
    int idx = blockIdx.x * blockDim.x + threadIdx.x;   // over BT*K2
    int c  = idx & 127;
    int bt = idx >> 7;
    int t  = bt & (Tt - 1);
    float acc = bias[c];
    #pragma unroll
    for (int j = 0; j < 4; j++) {
        int tt = t - 3 + j;
        if (tt >= 0)
            acc += beta[(size_t)(bt - 3 + j) * 128 + c] * w[c * 4 + j];
    }
    out[idx] = acc / (1.f + expf(-acc));               // silu
}

// ---------------- fused SSD (anti-causal reverse scan) + coupling + eig --------
// eig written tf32-rounded (feeds out_proj GEMM directly).
__global__ void __launch_bounds__(256)
ssd_fused_kernel(const float* __restrict__ beta_a,
                 const float* __restrict__ log_decay,
                 const float* __restrict__ freq,
                 const float* __restrict__ coupling,
                 float* __restrict__ eig)
{
    __shared__ float sb[64 * 128];
    __shared__ float scoup[Hh * Khd * Khd];
    int b  = blockIdx.x >> 6;
    int ch = blockIdx.x & 63;
    size_t base = (size_t)(b * Tt + ch * 64) * 128;
    const float4* src = (const float4*)(beta_a + base);
    for (int i = threadIdx.x; i < 64 * 128 / 4; i += 256)
        ((float4*)sb)[i] = src[i];
    for (int i = threadIdx.x; i < Hh * Khd * Khd; i += 256)
        scoup[i] = coupling[i];
    __syncthreads();

    if (threadIdx.x < 64) {
        int k = threadIdx.x;
        float mag = 1.f / (1.f + expf(-log_decay[k]));
        float f   = freq[k];
        float lr = mag * cosf(f), li = mag * sinf(f);
        float zr = 0.f, zi = 0.f;
        for (int i = 63; i >= 0; i--) {
            float br = sb[i * 128 + k];
            float bi = sb[i * 128 + 64 + k];
            float nr = lr * zr - li * zi + br;
            float ni = lr * zi + li * zr + bi;
            zr = nr; zi = ni;
            sb[i * 128 + k]      = zr;
            sb[i * 128 + 64 + k] = zi;
        }
        if (ch > 0) {
            sb[k]      += beta_a[base - 128 + k];
            sb[64 + k] += beta_a[base - 128 + 64 + k];
        }
    }
    __syncthreads();

    for (int task = threadIdx.x; task < 64 * 64; task += 256) {
        int i  = task >> 6;
        int ko = task & 63;
        int h = ko >> 4, j = ko & 15;
        const float* cw = scoup + h * (Khd * Khd) + j * Khd;
        const float* rowr = sb + i * 128 + h * Khd;
        const float* rowi = rowr + 64;
        float or_ = 0.f, oi_ = 0.f;
        #pragma unroll
        for (int kk = 0; kk < Khd; kk++) {
            float w = cw[kk];
            or_ += w * rowr[kk];
            oi_ += w * rowi[kk];
        }
        size_t e = (size_t)(b * Tt + ch * 64 + i) * 128;
        eig[e + ko]      = roundtf(or_);
        eig[e + 64 + ko] = roundtf(oi_);
    }
}

// ---------------- launcher ----------------
extern "C" void kernel_launch(void* const* d_in, const int* in_sizes, int n_in,
                              void* d_out, int out_size)
{
    const float* x          = (const float*)d_in[0];
    const float* in_proj_w  = (const float*)d_in[1];
    const float* conv_w     = (const float*)d_in[2];
    const float* conv_b     = (const float*)d_in[3];
    const float* log_decay  = (const float*)d_in[4];
    const float* frequency  = (const float*)d_in[5];
    const float* coupling   = (const float*)d_in[6];
    const float* out_proj_w = (const float*)d_in[7];
    const float* gate_w     = (const float*)d_in[8];
    const float* gate_b     = (const float*)d_in[9];
    const float* mlp_w1     = (const float*)d_in[10];
    const float* mlp_b1     = (const float*)d_in[11];
    const float* mlp_w2     = (const float*)d_in[12];
    const float* mlp_b2     = (const float*)d_in[13];
    const float* ln1_g      = (const float*)d_in[14];
    const float* ln1_b      = (const float*)d_in[15];
    const float* ln2_g      = (const float*)d_in[16];
    const float* ln2_b      = (const float*)d_in[17];

    float* out = (float*)d_out;
    float* eig = out + OUT_ELEMS;

    float *xn, *beta_l, *beta_a, *hb, *x1, *xn2, *hidden;
    float *w_in, *w_out, *w_gate, *w_m1, *w_m2;
    cudaGetSymbolAddress((void**)&xn,     g_xn);
    cudaGetSymbolAddress((void**)&beta_l, g_beta_l);
    cudaGetSymbolAddress((void**)&beta_a, g_beta_a);
    cudaGetSymbolAddress((void**)&hb,     g_hbuf);
    cudaGetSymbolAddress((void**)&x1,     g_x1);
    cudaGetSymbolAddress((void**)&xn2,    g_xn2);
    cudaGetSymbolAddress((void**)&hidden, g_hidden);
    cudaGetSymbolAddress((void**)&w_in,   g_w_in);
    cudaGetSymbolAddress((void**)&w_out,  g_w_out);
    cudaGetSymbolAddress((void**)&w_gate, g_w_gate);
    cudaGetSymbolAddress((void**)&w_m1,   g_w_m1);
    cudaGetSymbolAddress((void**)&w_m2,   g_w_m2);

    // raise dynamic smem limit (idempotent; host-side, capture-safe)
    cudaFuncSetAttribute(gemm_tf32_kernel<0>, cudaFuncAttributeMaxDynamicSharedMemorySize, SMEM_BYTES);
    cudaFuncSetAttribute(gemm_tf32_kernel<1>, cudaFuncAttributeMaxDynamicSharedMemorySize, SMEM_BYTES);
    cudaFuncSetAttribute(gemm_tf32_kernel<2>, cudaFuncAttributeMaxDynamicSharedMemorySize, SMEM_BYTES);
    cudaFuncSetAttribute(gemm_tf32_kernel<3>, cudaFuncAttributeMaxDynamicSharedMemorySize, SMEM_BYTES);

    // 0. round weights to tf32 copies
    round_tf32_kernel<<<(K2*Dm + 255)/256, 256>>>(in_proj_w, w_in, K2*Dm);
    round_tf32_kernel<<<(Dm*K2 + 255)/256, 256>>>(out_proj_w, w_out, Dm*K2);
    round_tf32_kernel<<<(Dm*Dm + 255)/256, 256>>>(gate_w, w_gate, Dm*Dm);
    round_tf32_kernel<<<(MLP*Dm + 255)/256, 256>>>(mlp_w1, w_m1, MLP*Dm);
    round_tf32_kernel<<<(Dm*MLP + 255)/256, 256>>>(mlp_w2, w_m2, Dm*MLP);

    // 1. xn = roundtf(LN1(x))
    ln_kernel<<<BT, 256>>>(x, xn, ln1_g, ln1_b);
    // 2. beta_lin = xn @ in_proj_w.T
    gemm_tf32_kernel<0><<<dim3(1, 128), 256, SMEM_BYTES>>>(xn, w_in, beta_l, BT, 128, 1024,
                                                           nullptr, nullptr, nullptr);
    // 3. beta = silu(causal depthwise conv + bias)
    conv_silu_kernel<<<(BT * K2) / 256, 256>>>(beta_l, conv_w, conv_b, beta_a);
    // 4. SSD (anti-causal reverse scan + carry + coupling) -> eig (tf32-rounded)
    ssd_fused_kernel<<<Bb * NCH, 256>>>(beta_a, log_decay, frequency, coupling, eig);
    // 5. h = eig @ out_proj_w.T
    gemm_tf32_kernel<0><<<dim3(8, 128), 256, SMEM_BYTES>>>(eig, w_out, hb, BT, 1024, 128,
                                                           nullptr, nullptr, nullptr);
    // 6. x1 = x + sigmoid(xn @ gate_w.T + gate_b) * h
    gemm_tf32_kernel<2><<<dim3(8, 128), 256, SMEM_BYTES>>>(xn, w_gate, x1, BT, 1024, 1024,
                                                           gate_b, x, hb);
    // 7. xn2 = roundtf(LN2(x1))
    ln_kernel<<<BT, 256>>>(x1, xn2, ln2_g, ln2_b);
    // 8. hidden = roundtf(silu(xn2 @ mlp_w1.T + b1))
    gemm_tf32_kernel<1><<<dim3(32, 128), 256, SMEM_BYTES>>>(xn2, w_m1, hidden, BT, 4096, 1024,
                                                            mlp_b1, nullptr, nullptr);
    // 9. out = x1 + hidden @ mlp_w2.T + b2
    gemm_tf32_kernel<3><<<dim3(8, 128), 256, SMEM_BYTES>>>(hidden, w_m2, out, BT, 1024, 4096,
                                                           mlp_b2, x1, nullptr);
}

// round 8
// speedup vs baseline: 3.1947x; 1.0846x over previous
#include <cuda_runtime.h>
#include <math.h>

// Shapes (fixed by the problem)
#define Bb   4
#define Tt   4096
#define Dm   1024
#define Kk   64
#define K2   128
#define Hh   4
#define Khd  16
#define NCH  64
#define BT   (Bb*Tt)       // 16384
#define MLP  4096
#define OUT_ELEMS (BT*Dm)  // 16777216

#define STAGES 3
#define TILE_BYTES 16384                         // 128 rows x 32 floats
#define SMEM_BYTES (STAGES * 2 * TILE_BYTES)     // 98304

// ---------------- scratch (static device memory; no allocation) ----------------
__device__ float g_xn     [BT*Dm];
__device__ float g_beta_l [BT*K2];
__device__ float g_beta_a [BT*K2];
__device__ float g_hbuf   [BT*Dm];
__device__ float g_x1     [BT*Dm];
__device__ float g_xn2    [BT*Dm];
__device__ float g_hidden [BT*MLP];
// tf32-rounded weight copies
__device__ float g_w_in   [K2*Dm];
__device__ float g_w_out  [Dm*K2];
__device__ float g_w_gate [Dm*Dm];
__device__ float g_w_m1   [MLP*Dm];
__device__ float g_w_m2   [Dm*MLP];

// ---------------- helpers ----------------
__device__ __forceinline__ unsigned f2tf(float f) {
    unsigned u;
    asm("cvt.rna.tf32.f32 %0, %1;" : "=r"(u) : "f"(f));
    return u;
}
__device__ __forceinline__ float roundtf(float f) { return __uint_as_float(f2tf(f)); }

__device__ __forceinline__ void cp_async16(void* smem_dst, const void* gptr) {
    unsigned saddr = (unsigned)__cvta_generic_to_shared(smem_dst);
    asm volatile("cp.async.cg.shared.global [%0], [%1], 16;\n" :: "r"(saddr), "l"(gptr));
}
__device__ __forceinline__ void cp_commit() { asm volatile("cp.async.commit_group;\n"); }
__device__ __forceinline__ void cp_wait1()  { asm volatile("cp.async.wait_group 1;\n"); }

__device__ __forceinline__ void ldsm_x4(unsigned& r0, unsigned& r1, unsigned& r2, unsigned& r3,
                                        unsigned saddr) {
    asm volatile("ldmatrix.sync.aligned.m8n8.x4.shared.b16 {%0,%1,%2,%3}, [%4];"
                 : "=r"(r0), "=r"(r1), "=r"(r2), "=r"(r3) : "r"(saddr));
}

// ---------------- weight rounding ----------------
__global__ void round_tf32_kernel(const float* __restrict__ in, float* __restrict__ out, int n)
{
    int i = blockIdx.x * blockDim.x + threadIdx.x;
    if (i < n) out[i] = roundtf(in[i]);
}

// ---------------- LayerNorm (writes tf32-rounded output) ----------------
__global__ void ln_kernel(const float* __restrict__ in, float* __restrict__ out,
                          const float* __restrict__ g, const float* __restrict__ bta)
{
    int row = blockIdx.x;
    const float4* p = (const float4*)(in + (size_t)row * Dm);
    float4 v = p[threadIdx.x];
    float s  = v.x + v.y + v.z + v.w;
    float ss = v.x*v.x + v.y*v.y + v.z*v.z + v.w*v.w;
    #pragma unroll
    for (int o = 16; o > 0; o >>= 1) {
        s  += __shfl_down_sync(0xffffffffu, s,  o);
        ss += __shfl_down_sync(0xffffffffu, ss, o);
    }
    __shared__ float rs[8], rss[8];
    __shared__ float smean, srstd;
    int warp = threadIdx.x >> 5, lane = threadIdx.x & 31;
    if (lane == 0) { rs[warp] = s; rss[warp] = ss; }
    __syncthreads();
    if (threadIdx.x == 0) {
        float ts = 0.f, tss = 0.f;
        #pragma unroll
        for (int w = 0; w < 8; w++) { ts += rs[w]; tss += rss[w]; }
        float mean = ts * (1.f/Dm);
        float var  = tss * (1.f/Dm) - mean*mean;
        smean = mean;
        srstd = rsqrtf(var + 1e-5f);
    }
    __syncthreads();
    float mean = smean, rstd = srstd;
    float4 gg = ((const float4*)g)[threadIdx.x];
    float4 bb = ((const float4*)bta)[threadIdx.x];
    float4 o;
    o.x = roundtf((v.x - mean) * rstd * gg.x + bb.x);
    o.y = roundtf((v.y - mean) * rstd * gg.y + bb.y);
    o.z = roundtf((v.z - mean) * rstd * gg.z + bb.z);
    o.w = roundtf((v.w - mean) * rstd * gg.w + bb.w);
    ((float4*)(out + (size_t)row * Dm))[threadIdx.x] = o;
}

// ---------------- tf32 tensor GEMM, 3-stage cp.async pipeline + ldmatrix --------
// C[m][n] = sum_k A[m][k]*B[n][k]; A,B already tf32-rounded. Kd % 32 == 0.
// Block 128x128, 8 warps (2x4), warp tile 64x32, mma m16n8k8, frags via ldmatrix.
// EPI 0: C = acc
// EPI 1: C = roundtf(silu(acc + bias[n]))
// EPI 2: C = aux1 + sigmoid(acc + bias[n]) * aux2
// EPI 3: C = acc + bias[n] + aux1
template<int EPI>
__global__ void __launch_bounds__(256)
gemm_tf32_kernel(const float* __restrict__ A, const float* __restrict__ Bw,
                 float* __restrict__ C, int M, int N, int Kd,
                 const float* __restrict__ bias,
                 const float* __restrict__ aux1, const float* __restrict__ aux2)
{
    extern __shared__ float dsm[];
    const unsigned smem_u32 = (unsigned)__cvta_generic_to_shared(dsm);

    const int tid  = threadIdx.x;
    const int warp = tid >> 5, lane = tid & 31;
    const int wr = warp >> 2;               // 0..1
    const int wc = warp & 3;                // 0..3
    const int brow = blockIdx.y * 128, bcol = blockIdx.x * 128;

    // loader mapping: row = tid>>1, chunk base = (tid&1)*4 (each chunk = 4 floats)
    const int lr  = tid >> 1;
    const int lcb = (tid & 1) * 4;
    const float* Arow = A  + (size_t)(brow + lr) * Kd;
    const float* Brow = Bw + (size_t)(bcol + lr) * Kd;

    const int KT = Kd >> 5;                 // k-chunks of 32

    auto issue = [&](int buf, int k0) {
        float* Atile = dsm + buf * (128 * 32);
        float* Btile = dsm + (STAGES + buf) * (128 * 32);
        #pragma unroll
        for (int i = 0; i < 4; i++) {
            int cc = lcb + i;
            int dst = lr * 32 + (((cc ^ lr) & 7) << 2);
            cp_async16(Atile + dst, Arow + k0 + cc * 4);
            cp_async16(Btile + dst, Brow + k0 + cc * 4);
        }
    };

    float acc[4][4][4];
    #pragma unroll
    for (int m = 0; m < 4; m++)
        #pragma unroll
        for (int n = 0; n < 4; n++)
            #pragma unroll
            for (int i = 0; i < 4; i++) acc[m][n][i] = 0.f;

    // prologue: stages 0,1
    issue(0, 0);  cp_commit();
    issue(1, 32); cp_commit();

    // ldmatrix per-lane addressing (byte offsets within a 128x32-float tile).
    const int lm = lane & 7;
    int aoff[4], ars[4];
    {
        int rowsel = (lane >> 3) & 1;
        #pragma unroll
        for (int mt = 0; mt < 4; mt++) {
            int row = wr*64 + mt*16 + rowsel*8 + lm;
            aoff[mt] = row * 128;            // bytes
            ars[mt]  = row & 7;
        }
    }
    const int ghA = lane >> 4;
    int boff[2], brs[2];
    {
        int rowsel = lane >> 4;
        #pragma unroll
        for (int p = 0; p < 2; p++) {
            int n = wc*32 + p*16 + rowsel*8 + lm;
            boff[p] = n * 128;
            brs[p]  = n & 7;
        }
    }
    const int ghB = (lane >> 3) & 1;

    const int ra = lane >> 2;
    const int c0 = lane & 3;

    for (int kt = 0; kt < KT; kt++) {
        cp_wait1();
        __syncthreads();                    // single barrier per chunk
        if (kt + 2 < KT) issue((kt + 2) % STAGES, (kt + 2) * 32);
        cp_commit();

        const int buf = kt % STAGES;
        const unsigned Abase = smem_u32 + buf * TILE_BYTES;
        const unsigned Bbase = smem_u32 + (STAGES + buf) * TILE_BYTES;

        #pragma unroll
        for (int ks = 0; ks < 4; ks++) {
            unsigned af[4][4], bf[4][2];
            const int gA = 2*ks + ghA;
            #pragma unroll
            for (int mt = 0; mt < 4; mt++) {
                unsigned ad = Abase + aoff[mt] + (unsigned)(((gA ^ ars[mt]) & 7) << 4);
                ldsm_x4(af[mt][0], af[mt][1], af[mt][2], af[mt][3], ad);
            }
            const int gB = 2*ks + ghB;
            #pragma unroll
            for (int p = 0; p < 2; p++) {
                unsigned bd = Bbase + boff[p] + (unsigned)(((gB ^ brs[p]) & 7) << 4);
                ldsm_x4(bf[2*p][0], bf[2*p][1], bf[2*p+1][0], bf[2*p+1][1], bd);
            }
            #pragma unroll
            for (int mt = 0; mt < 4; mt++)
                #pragma unroll
                for (int nt = 0; nt < 4; nt++)
                    asm volatile(
                        "mma.sync.aligned.m16n8k8.row.col.f32.tf32.tf32.f32 "
                        "{%0,%1,%2,%3}, {%4,%5,%6,%7}, {%8,%9}, {%0,%1,%2,%3};"
                        : "+f"(acc[mt][nt][0]), "+f"(acc[mt][nt][1]),
                          "+f"(acc[mt][nt][2]), "+f"(acc[mt][nt][3])
                        : "r"(af[mt][0]), "r"(af[mt][1]), "r"(af[mt][2]), "r"(af[mt][3]),
                          "r"(bf[nt][0]), "r"(bf[nt][1]));
        }
    }

    // epilogue: thread owns (row, col..col+1) pairs
    #pragma unroll
    for (int mt = 0; mt < 4; mt++) {
        #pragma unroll
        for (int half = 0; half < 2; half++) {
            int row = brow + wr*64 + mt*16 + ra + half*8;
            #pragma unroll
            for (int nt = 0; nt < 4; nt++) {
                int col = bcol + wc*32 + nt*8 + c0*2;
                size_t idx = (size_t)row * N + col;
                float v0 = acc[mt][nt][half*2 + 0];
                float v1 = acc[mt][nt][half*2 + 1];
                float2 o;
                if (EPI == 0) {
                    o.x = v0; o.y = v1;
                } else if (EPI == 1) {
                    v0 += bias[col]; v1 += bias[col+1];
                    o.x = roundtf(v0 / (1.f + expf(-v0)));
                    o.y = roundtf(v1 / (1.f + expf(-v1)));
                } else if (EPI == 2) {
                    float g0 = 1.f / (1.f + expf(-(v0 + bias[col])));
                    float g1 = 1.f / (1.f + expf(-(v1 + bias[col+1])));
                    float2 a1v = *(const float2*)(aux1 + idx);
                    float2 a2v = *(const float2*)(aux2 + idx);
                    o.x = a1v.x + g0 * a2v.x;
                    o.y = a1v.y + g1 * a2v.y;
                } else { // EPI == 3
                    float2 a1v = *(const float2*)(aux1 + idx);
                    o.x = v0 + bias[col]   + a1v.x;
                    o.y = v1 + bias[col+1] + a1v.y;
                }
                *(float2*)(C + idx) = o;
            }
        }
    }
}

// ---------------- depthwise causal conv (4-tap) + bias + SiLU ----------------
__global__ void conv_silu_kernel(const float* __restrict__ beta,
                                 const float* __restrict__ w,
                                 const float* __restrict__ bias,
                                 float* __restrict__ out)
{
    int idx = blockIdx.x * blockDim.x + threadIdx.x;   // over BT*K2
    int c  = idx & 127;
    int bt = idx >> 7;
    int t  = bt & (Tt - 1);
    float acc = bias[c];
    #pragma unroll
    for (int j = 0; j < 4; j++) {
        int tt = t - 3 + j;
        if (tt >= 0)
            acc += beta[(size_t)(bt - 3 + j) * 128 + c] * w[c * 4 + j];
    }
    out[idx] = acc / (1.f + expf(-acc));               // silu
}

// ---------------- fused SSD (anti-causal reverse scan) + coupling + eig --------
__global__ void __launch_bounds__(256)
ssd_fused_kernel(const float* __restrict__ beta_a,
                 const float* __restrict__ log_decay,
                 const float* __restrict__ freq,
                 const float* __restrict__ coupling,
                 float* __restrict__ eig)
{
    __shared__ float sb[64 * 128];
    __shared__ float scoup[Hh * Khd * Khd];
    int b  = blockIdx.x >> 6;
    int ch = blockIdx.x & 63;
    size_t base = (size_t)(b * Tt + ch * 64) * 128;
    const float4* src = (const float4*)(beta_a + base);
    for (int i = threadIdx.x; i < 64 * 128 / 4; i += 256)
        ((float4*)sb)[i] = src[i];
    for (int i = threadIdx.x; i < Hh * Khd * Khd; i += 256)
        scoup[i] = coupling[i];
    __syncthreads();

    if (threadIdx.x < 64) {
        int k = threadIdx.x;
        float mag = 1.f / (1.f + expf(-log_decay[k]));
        float f   = freq[k];
        float lr = mag * cosf(f), li = mag * sinf(f);
        float zr = 0.f, zi = 0.f;
        for (int i = 63; i >= 0; i--) {
            float br = sb[i * 128 + k];
            float bi = sb[i * 128 + 64 + k];
            float nr = lr * zr - li * zi + br;
            float ni = lr * zi + li * zr + bi;
            zr = nr; zi = ni;
            sb[i * 128 + k]      = zr;
            sb[i * 128 + 64 + k] = zi;
        }
        if (ch > 0) {
            sb[k]      += beta_a[base - 128 + k];
            sb[64 + k] += beta_a[base - 128 + 64 + k];
        }
    }
    __syncthreads();

    for (int task = threadIdx.x; task < 64 * 64; task += 256) {
        int i  = task >> 6;
        int ko = task & 63;
        int h = ko >> 4, j = ko & 15;
        const float* cw = scoup + h * (Khd * Khd) + j * Khd;
        const float* rowr = sb + i * 128 + h * Khd;
        const float* rowi = rowr + 64;
        float or_ = 0.f, oi_ = 0.f;
        #pragma unroll
        for (int kk = 0; kk < Khd; kk++) {
            float w = cw[kk];
            or_ += w * rowr[kk];
            oi_ += w * rowi[kk];
        }
        size_t e = (size_t)(b * Tt + ch * 64 + i) * 128;
        eig[e + ko]      = roundtf(or_);
        eig[e + 64 + ko] = roundtf(oi_);
    }
}

// ---------------- launcher ----------------
extern "C" void kernel_launch(void* const* d_in, const int* in_sizes, int n_in,
                              void* d_out, int out_size)
{
    const float* x          = (const float*)d_in[0];
    const float* in_proj_w  = (const float*)d_in[1];
    const float* conv_w     = (const float*)d_in[2];
    const float* conv_b     = (const float*)d_in[3];
    const float* log_decay  = (const float*)d_in[4];
    const float* frequency  = (const float*)d_in[5];
    const float* coupling   = (const float*)d_in[6];
    const float* out_proj_w = (const float*)d_in[7];
    const float* gate_w     = (const float*)d_in[8];
    const float* gate_b     = (const float*)d_in[9];
    const float* mlp_w1     = (const float*)d_in[10];
    const float* mlp_b1     = (const float*)d_in[11];
    const float* mlp_w2     = (const float*)d_in[12];
    const float* mlp_b2     = (const float*)d_in[13];
    const float* ln1_g      = (const float*)d_in[14];
    const float* ln1_b      = (const float*)d_in[15];
    const float* ln2_g      = (const float*)d_in[16];
    const float* ln2_b      = (const float*)d_in[17];

    float* out = (float*)d_out;
    float* eig = out + OUT_ELEMS;

    float *xn, *beta_l, *beta_a, *hb, *x1, *xn2, *hidden;
    float *w_in, *w_out, *w_gate, *w_m1, *w_m2;
    cudaGetSymbolAddress((void**)&xn,     g_xn);
    cudaGetSymbolAddress((void**)&beta_l, g_beta_l);
    cudaGetSymbolAddress((void**)&beta_a, g_beta_a);
    cudaGetSymbolAddress((void**)&hb,     g_hbuf);
    cudaGetSymbolAddress((void**)&x1,     g_x1);
    cudaGetSymbolAddress((void**)&xn2,    g_xn2);
    cudaGetSymbolAddress((void**)&hidden, g_hidden);
    cudaGetSymbolAddress((void**)&w_in,   g_w_in);
    cudaGetSymbolAddress((void**)&w_out,  g_w_out);
    cudaGetSymbolAddress((void**)&w_gate, g_w_gate);
    cudaGetSymbolAddress((void**)&w_m1,   g_w_m1);
    cudaGetSymbolAddress((void**)&w_m2,   g_w_m2);

    cudaFuncSetAttribute(gemm_tf32_kernel<0>, cudaFuncAttributeMaxDynamicSharedMemorySize, SMEM_BYTES);
    cudaFuncSetAttribute(gemm_tf32_kernel<1>, cudaFuncAttributeMaxDynamicSharedMemorySize, SMEM_BYTES);
    cudaFuncSetAttribute(gemm_tf32_kernel<2>, cudaFuncAttributeMaxDynamicSharedMemorySize, SMEM_BYTES);
    cudaFuncSetAttribute(gemm_tf32_kernel<3>, cudaFuncAttributeMaxDynamicSharedMemorySize, SMEM_BYTES);

    // 0. round weights to tf32 copies
    round_tf32_kernel<<<(K2*Dm + 255)/256, 256>>>(in_proj_w, w_in, K2*Dm);
    round_tf32_kernel<<<(Dm*K2 + 255)/256, 256>>>(out_proj_w, w_out, Dm*K2);
    round_tf32_kernel<<<(Dm*Dm + 255)/256, 256>>>(gate_w, w_gate, Dm*Dm);
    round_tf32_kernel<<<(MLP*Dm + 255)/256, 256>>>(mlp_w1, w_m1, MLP*Dm);
    round_tf32_kernel<<<(Dm*MLP + 255)/256, 256>>>(mlp_w2, w_m2, Dm*MLP);

    // 1. xn = roundtf(LN1(x))
    ln_kernel<<<BT, 256>>>(x, xn, ln1_g, ln1_b);
    // 2. beta_lin = xn @ in_proj_w.T
    gemm_tf32_kernel<0><<<dim3(1, 128), 256, SMEM_BYTES>>>(xn, w_in, beta_l, BT, 128, 1024,
                                                           nullptr, nullptr, nullptr);
    // 3. beta = silu(causal depthwise conv + bias)
    conv_silu_kernel<<<(BT * K2) / 256, 256>>>(beta_l, conv_w, conv_b, beta_a);
    // 4. SSD (anti-causal reverse scan + carry + coupling) -> eig (tf32-rounded)
    ssd_fused_kernel<<<Bb * NCH, 256>>>(beta_a, log_decay, frequency, coupling, eig);
    // 5. h = eig @ out_proj_w.T
    gemm_tf32_kernel<0><<<dim3(8, 128), 256, SMEM_BYTES>>>(eig, w_out, hb, BT, 1024, 128,
                                                           nullptr, nullptr, nullptr);
    // 6. x1 = x + sigmoid(xn @ gate_w.T + gate_b) * h
    gemm_tf32_kernel<2><<<dim3(8, 128), 256, SMEM_BYTES>>>(xn, w_gate, x1, BT, 1024, 1024,
                                                           gate_b, x, hb);
    // 7. xn2 = roundtf(LN2(x1))
    ln_kernel<<<BT, 256>>>(x1, xn2, ln2_g, ln2_b);
    // 8. hidden = roundtf(silu(xn2 @ mlp_w1.T + b1))
    gemm_tf32_kernel<1><<<dim3(32, 128), 256, SMEM_BYTES>>>(xn2, w_m1, hidden, BT, 4096, 1024,
                                                            mlp_b1, nullptr, nullptr);
    // 9. out = x1 + hidden @ mlp_w2.T + b2
    gemm_tf32_kernel<3><<<dim3(8, 128), 256, SMEM_BYTES>>>(hidden, w_m2, out, BT, 1024, 4096,
                                                           mlp_b2, x1, nullptr);
}

// round 11
// speedup vs baseline: 5.7033x; 1.7852x over previous
#include <cuda_runtime.h>
#include <cuda_fp16.h>
#include <math.h>
#include <stdint.h>

// Shapes (fixed by the problem)
#define Bb   4
#define Tt   4096
#define Dm   1024
#define Kk   64
#define K2   128
#define Hh   4
#define Khd  16
#define NCH  64
#define BT   (Bb*Tt)       // 16384
#define MLP  4096
#define OUT_ELEMS (BT*Dm)  // 16777216

#define STAGES 3
#define TILE_BYTES 16384                         // 128 rows x 128 bytes (64 halves)
#define SMEM_BYTES (STAGES * 2 * TILE_BYTES)     // 98304

// ---------------- scratch (static device memory; no allocation) ----------------
__device__ __half g_xn     [BT*Dm];
__device__ float  g_beta_l [BT*K2];
__device__ float  g_beta_a [BT*K2];
__device__ __half g_eig_h  [BT*K2];
__device__ float  g_hbuf   [BT*Dm];
__device__ float  g_x1     [BT*Dm];
__device__ __half g_xn2    [BT*Dm];
__device__ __half g_hidden [BT*MLP];
// fp16 weight copies
__device__ __half g_w_in   [K2*Dm];
__device__ __half g_w_out  [Dm*K2];
__device__ __half g_w_gate [Dm*Dm];
__device__ __half g_w_m1   [MLP*Dm];
__device__ __half g_w_m2   [Dm*MLP];

// ---------------- helpers ----------------
__device__ __forceinline__ void cp_async16(void* smem_dst, const void* gptr) {
    unsigned saddr = (unsigned)__cvta_generic_to_shared(smem_dst);
    asm volatile("cp.async.cg.shared.global [%0], [%1], 16;\n" :: "r"(saddr), "l"(gptr));
}
__device__ __forceinline__ void cp_commit() { asm volatile("cp.async.commit_group;\n"); }
__device__ __forceinline__ void cp_wait1()  { asm volatile("cp.async.wait_group 1;\n"); }

__device__ __forceinline__ void ldsm_x4(unsigned& r0, unsigned& r1, unsigned& r2, unsigned& r3,
                                        unsigned saddr) {
    asm volatile("ldmatrix.sync.aligned.m8n8.x4.shared.b16 {%0,%1,%2,%3}, [%4];"
                 : "=r"(r0), "=r"(r1), "=r"(r2), "=r"(r3) : "r"(saddr));
}

// ---------------- weight conversion fp32 -> fp16 ----------------
__global__ void round_half_kernel(const float* __restrict__ in, __half* __restrict__ out, int n)
{
    int i = blockIdx.x * blockDim.x + threadIdx.x;
    if (i < n) out[i] = __float2half_rn(in[i]);
}

// ---------------- LayerNorm (writes fp16 output) ----------------
__global__ void ln_kernel(const float* __restrict__ in, __half* __restrict__ out,
                          const float* __restrict__ g, const float* __restrict__ bta)
{
    int row = blockIdx.x;
    const float4* p = (const float4*)(in + (size_t)row * Dm);
    float4 v = p[threadIdx.x];
    float s  = v.x + v.y + v.z + v.w;
    float ss = v.x*v.x + v.y*v.y + v.z*v.z + v.w*v.w;
    #pragma unroll
    for (int o = 16; o > 0; o >>= 1) {
        s  += __shfl_down_sync(0xffffffffu, s,  o);
        ss += __shfl_down_sync(0xffffffffu, ss, o);
    }
    __shared__ float rs[8], rss[8];
    __shared__ float smean, srstd;
    int warp = threadIdx.x >> 5, lane = threadIdx.x & 31;
    if (lane == 0) { rs[warp] = s; rss[warp] = ss; }
    __syncthreads();
    if (threadIdx.x == 0) {
        float ts = 0.f, tss = 0.f;
        #pragma unroll
        for (int w = 0; w < 8; w++) { ts += rs[w]; tss += rss[w]; }
        float mean = ts * (1.f/Dm);
        float var  = tss * (1.f/Dm) - mean*mean;
        smean = mean;
        srstd = rsqrtf(var + 1e-5f);
    }
    __syncthreads();
    float mean = smean, rstd = srstd;
    float4 gg = ((const float4*)g)[threadIdx.x];
    float4 bb = ((const float4*)bta)[threadIdx.x];
    __half2 h0 = __floats2half2_rn((v.x - mean) * rstd * gg.x + bb.x,
                                   (v.y - mean) * rstd * gg.y + bb.y);
    __half2 h1 = __floats2half2_rn((v.z - mean) * rstd * gg.z + bb.z,
                                   (v.w - mean) * rstd * gg.w + bb.w);
    __half2* dst = (__half2*)(out + (size_t)row * Dm) + threadIdx.x * 2;
    dst[0] = h0;
    dst[1] = h1;
}

// ---------------- fp16 tensor GEMM, 3-stage cp.async pipeline + ldmatrix --------
// C[m][n] = sum_k A[m][k]*B[n][k]; A,B fp16 row-major, Kd % 64 == 0.
// Block 128x128, 8 warps (2x4), warp tile 64x32, mma m16n8k16 (fp32 accum).
// EPI 0: C = acc
// EPI 1: C = silu(acc + bias[n])
// EPI 2: C = aux1 + sigmoid(acc + bias[n]) * aux2
// EPI 3: C = acc + bias[n] + aux1
// HOUT: store as __half (else float)
template<int EPI, bool HOUT>
__global__ void __launch_bounds__(256)
gemm_fp16_kernel(const __half* __restrict__ A, const __half* __restrict__ Bw,
                 void* __restrict__ Cv, int M, int N, int Kd,
                 const float* __restrict__ bias,
                 const float* __restrict__ aux1, const float* __restrict__ aux2)
{
    extern __shared__ char dsm[];
    const unsigned smem_u32 = (unsigned)__cvta_generic_to_shared(dsm);

    const int tid  = threadIdx.x;
    const int warp = tid >> 5, lane = tid & 31;
    const int wr = warp >> 2;               // 0..1
    const int wc = warp & 3;                // 0..3
    const int brow = blockIdx.y * 128, bcol = blockIdx.x * 128;

    // loader: row = tid>>1, group base = (tid&1)*4; each group = 16B = 8 halves
    const int lr  = tid >> 1;
    const int lcb = (tid & 1) * 4;
    const __half* Arow = A  + (size_t)(brow + lr) * Kd;
    const __half* Brow = Bw + (size_t)(bcol + lr) * Kd;

    const int KT = Kd >> 6;                 // k-chunks of 64 halves

    auto issue = [&](int buf, int k0) {
        char* Atile = dsm + buf * TILE_BYTES;
        char* Btile = dsm + (STAGES + buf) * TILE_BYTES;
        #pragma unroll
        for (int i = 0; i < 4; i++) {
            int cc = lcb + i;
            int dst = lr * 128 + (((cc ^ lr) & 7) << 4);
            cp_async16(Atile + dst, Arow + k0 + cc * 8);
            cp_async16(Btile + dst, Brow + k0 + cc * 8);
        }
    };

    float acc[4][4][4];
    #pragma unroll
    for (int m = 0; m < 4; m++)
        #pragma unroll
        for (int n = 0; n < 4; n++)
            #pragma unroll
            for (int i = 0; i < 4; i++) acc[m][n][i] = 0.f;

    issue(0, 0);  cp_commit();
    issue(1, 64); cp_commit();

    // ldmatrix per-lane addressing (byte offsets within a 128x128B tile).
    const int lm = lane & 7;
    int aoff[4], ars[4];
    {
        int rowsel = (lane >> 3) & 1;
        #pragma unroll
        for (int mt = 0; mt < 4; mt++) {
            int row = wr*64 + mt*16 + rowsel*8 + lm;
            aoff[mt] = row * 128;
            ars[mt]  = row & 7;
        }
    }
    const int ghA = lane >> 4;
    int boff[2], brs[2];
    {
        int rowsel = lane >> 4;
        #pragma unroll
        for (int p = 0; p < 2; p++) {
            int n = wc*32 + p*16 + rowsel*8 + lm;
            boff[p] = n * 128;
            brs[p]  = n & 7;
        }
    }
    const int ghB = (lane >> 3) & 1;

    const int ra = lane >> 2;
    const int c0 = lane & 3;

    for (int kt = 0; kt < KT; kt++) {
        cp_wait1();
        __syncthreads();                    // single barrier per chunk
        if (kt + 2 < KT) issue((kt + 2) % STAGES, (kt + 2) * 64);
        cp_commit();

        const int buf = kt % STAGES;
        const unsigned Abase = smem_u32 + buf * TILE_BYTES;
        const unsigned Bbase = smem_u32 + (STAGES + buf) * TILE_BYTES;

        #pragma unroll
        for (int ks = 0; ks < 4; ks++) {    // K=16 per step, 2 groups per step
            unsigned af[4][4], bf[4][2];
            const int gA = 2*ks + ghA;
            #pragma unroll
            for (int mt = 0; mt < 4; mt++) {
                unsigned ad = Abase + aoff[mt] + (unsigned)(((gA ^ ars[mt]) & 7) << 4);
                ldsm_x4(af[mt][0], af[mt][1], af[mt][2], af[mt][3], ad);
            }
            const int gB = 2*ks + ghB;
            #pragma unroll
            for (int p = 0; p < 2; p++) {
                unsigned bd = Bbase + boff[p] + (unsigned)(((gB ^ brs[p]) & 7) << 4);
                ldsm_x4(bf[2*p][0], bf[2*p][1], bf[2*p+1][0], bf[2*p+1][1], bd);
            }
            #pragma unroll
            for (int mt = 0; mt < 4; mt++)
                #pragma unroll
                for (int nt = 0; nt < 4; nt++)
                    asm volatile(
                        "mma.sync.aligned.m16n8k16.row.col.f32.f16.f16.f32 "
                        "{%0,%1,%2,%3}, {%4,%5,%6,%7}, {%8,%9}, {%0,%1,%2,%3};"
                        : "+f"(acc[mt][nt][0]), "+f"(acc[mt][nt][1]),
                          "+f"(acc[mt][nt][2]), "+f"(acc[mt][nt][3])
                        : "r"(af[mt][0]), "r"(af[mt][1]), "r"(af[mt][2]), "r"(af[mt][3]),
                          "r"(bf[nt][0]), "r"(bf[nt][1]));
        }
    }

    // epilogue: thread owns (row, col..col+1) pairs
    #pragma unroll
    for (int mt = 0; mt < 4; mt++) {
        #pragma unroll
        for (int half = 0; half < 2; half++) {
            int row = brow + wr*64 + mt*16 + ra + half*8;
            #pragma unroll
            for (int nt = 0; nt < 4; nt++) {
                int col = bcol + wc*32 + nt*8 + c0*2;
                size_t idx = (size_t)row * N + col;
                float v0 = acc[mt][nt][half*2 + 0];
                float v1 = acc[mt][nt][half*2 + 1];
                float2 o;
                if (EPI == 0) {
                    o.x = v0; o.y = v1;
                } else if (EPI == 1) {
                    v0 += bias[col]; v1 += bias[col+1];
                    o.x = v0 / (1.f + expf(-v0));
                    o.y = v1 / (1.f + expf(-v1));
                } else if (EPI == 2) {
                    float g0 = 1.f / (1.f + expf(-(v0 + bias[col])));
                    float g1 = 1.f / (1.f + expf(-(v1 + bias[col+1])));
                    float2 a1v = *(const float2*)(aux1 + idx);
                    float2 a2v = *(const float2*)(aux2 + idx);
                    o.x = a1v.x + g0 * a2v.x;
                    o.y = a1v.y + g1 * a2v.y;
                } else { // EPI == 3
                    float2 a1v = *(const float2*)(aux1 + idx);
                    o.x = v0 + bias[col]   + a1v.x;
                    o.y = v1 + bias[col+1] + a1v.y;
                }
                if (HOUT) {
                    *(__half2*)((__half*)Cv + idx) = __floats2half2_rn(o.x, o.y);
                } else {
                    *(float2*)((float*)Cv + idx) = o;
                }
            }
        }
    }
}

// ---------------- depthwise causal conv (4-tap) + bias + SiLU ----------------
__global__ void conv_silu_kernel(const float* __restrict__ beta,
                                 const float* __restrict__ w,
                                 const float* __restrict__ bias,
                                 float* __restrict__ out)
{
    int idx = blockIdx.x * blockDim.x + threadIdx.x;   // over BT*K2
    int c  = idx & 127;
    int bt = idx >> 7;
    int t  = bt & (Tt - 1);
    float acc = bias[c];
    #pragma unroll
    for (int j = 0; j < 4; j++) {
        int tt = t - 3 + j;
        if (tt >= 0)
            acc += beta[(size_t)(bt - 3 + j) * 128 + c] * w[c * 4 + j];
    }
    out[idx] = acc / (1.f + expf(-acc));               // silu
}

// ---------------- fused SSD (anti-causal reverse scan) + coupling + eig --------
// writes eig fp32 (checked output) + fp16 copy (feeds out_proj GEMM)
__global__ void __launch_bounds__(256)
ssd_fused_kernel(const float* __restrict__ beta_a,
                 const float* __restrict__ log_decay,
                 const float* __restrict__ freq,
                 const float* __restrict__ coupling,
                 float* __restrict__ eig,
                 __half* __restrict__ eig_h)
{
    __shared__ float sb[64 * 128];
    __shared__ float scoup[Hh * Khd * Khd];
    int b  = blockIdx.x >> 6;
    int ch = blockIdx.x & 63;
    size_t base = (size_t)(b * Tt + ch * 64) * 128;
    const float4* src = (const float4*)(beta_a + base);
    for (int i = threadIdx.x; i < 64 * 128 / 4; i += 256)
        ((float4*)sb)[i] = src[i];
    for (int i = threadIdx.x; i < Hh * Khd * Khd; i += 256)
        scoup[i] = coupling[i];
    __syncthreads();

    if (threadIdx.x < 64) {
        int k = threadIdx.x;
        float mag = 1.f / (1.f + expf(-log_decay[k]));
        float f   = freq[k];
        float lr = mag * cosf(f), li = mag * sinf(f);
        float zr = 0.f, zi = 0.f;
        for (int i = 63; i >= 0; i--) {
            float br = sb[i * 128 + k];
            float bi = sb[i * 128 + 64 + k];
            float nr = lr * zr - li * zi + br;
            float ni = lr * zi + li * zr + bi;
            zr = nr; zi = ni;
            sb[i * 128 + k]      = zr;
            sb[i * 128 + 64 + k] = zi;
        }
        if (ch > 0) {
            sb[k]      += beta_a[base - 128 + k];
            sb[64 + k] += beta_a[base - 128 + 64 + k];
        }
    }
    __syncthreads();

    for (int task = threadIdx.x; task < 64 * 64; task += 256) {
        int i  = task >> 6;
        int ko = task & 63;
        int h = ko >> 4, j = ko & 15;
        const float* cw = scoup + h * (Khd * Khd) + j * Khd;
        const float* rowr = sb + i * 128 + h * Khd;
        const float* rowi = rowr + 64;
        float or_ = 0.f, oi_ = 0.f;
        #pragma unroll
        for (int kk = 0; kk < Khd; kk++) {
            float w = cw[kk];
            or_ += w * rowr[kk];
            oi_ += w * rowi[kk];
        }
        size_t e = (size_t)(b * Tt + ch * 64 + i) * 128;
        eig[e + ko]      = or_;
        eig[e + 64 + ko] = oi_;
        eig_h[e + ko]      = __float2half_rn(or_);
        eig_h[e + 64 + ko] = __float2half_rn(oi_);
    }
}

// ---------------- launcher ----------------
extern "C" void kernel_launch(void* const* d_in, const int* in_sizes, int n_in,
                              void* d_out, int out_size)
{
    const float* x          = (const float*)d_in[0];
    const float* in_proj_w  = (const float*)d_in[1];
    const float* conv_w     = (const float*)d_in[2];
    const float* conv_b     = (const float*)d_in[3];
    const float* log_decay  = (const float*)d_in[4];
    const float* frequency  = (const float*)d_in[5];
    const float* coupling   = (const float*)d_in[6];
    const float* out_proj_w = (const float*)d_in[7];
    const float* gate_w     = (const float*)d_in[8];
    const float* gate_b     = (const float*)d_in[9];
    const float* mlp_w1     = (const float*)d_in[10];
    const float* mlp_b1     = (const float*)d_in[11];
    const float* mlp_w2     = (const float*)d_in[12];
    const float* mlp_b2     = (const float*)d_in[13];
    const float* ln1_g      = (const float*)d_in[14];
    const float* ln1_b      = (const float*)d_in[15];
    const float* ln2_g      = (const float*)d_in[16];
    const float* ln2_b      = (const float*)d_in[17];

    float* out = (float*)d_out;
    float* eig = out + OUT_ELEMS;

    __half *xn, *xn2, *hidden, *eig_h;
    float  *beta_l, *beta_a, *hb, *x1;
    __half *w_in, *w_out, *w_gate, *w_m1, *w_m2;
    cudaGetSymbolAddress((void**)&xn,     g_xn);
    cudaGetSymbolAddress((void**)&beta_l, g_beta_l);
    cudaGetSymbolAddress((void**)&beta_a, g_beta_a);
    cudaGetSymbolAddress((void**)&eig_h,  g_eig_h);
    cudaGetSymbolAddress((void**)&hb,     g_hbuf);
    cudaGetSymbolAddress((void**)&x1,     g_x1);
    cudaGetSymbolAddress((void**)&xn2,    g_xn2);
    cudaGetSymbolAddress((void**)&hidden, g_hidden);
    cudaGetSymbolAddress((void**)&w_in,   g_w_in);
    cudaGetSymbolAddress((void**)&w_out,  g_w_out);
    cudaGetSymbolAddress((void**)&w_gate, g_w_gate);
    cudaGetSymbolAddress((void**)&w_m1,   g_w_m1);
    cudaGetSymbolAddress((void**)&w_m2,   g_w_m2);

    cudaFuncSetAttribute(gemm_fp16_kernel<0,false>, cudaFuncAttributeMaxDynamicSharedMemorySize, SMEM_BYTES);
    cudaFuncSetAttribute(gemm_fp16_kernel<1,true>,  cudaFuncAttributeMaxDynamicSharedMemorySize, SMEM_BYTES);
    cudaFuncSetAttribute(gemm_fp16_kernel<2,false>, cudaFuncAttributeMaxDynamicSharedMemorySize, SMEM_BYTES);
    cudaFuncSetAttribute(gemm_fp16_kernel<3,false>, cudaFuncAttributeMaxDynamicSharedMemorySize, SMEM_BYTES);

    // 0. convert weights to fp16
    round_half_kernel<<<(K2*Dm + 255)/256, 256>>>(in_proj_w, w_in, K2*Dm);
    round_half_kernel<<<(Dm*K2 + 255)/256, 256>>>(out_proj_w, w_out, Dm*K2);
    round_half_kernel<<<(Dm*Dm + 255)/256, 256>>>(gate_w, w_gate, Dm*Dm);
    round_half_kernel<<<(MLP*Dm + 255)/256, 256>>>(mlp_w1, w_m1, MLP*Dm);
    round_half_kernel<<<(Dm*MLP + 255)/256, 256>>>(mlp_w2, w_m2, Dm*MLP);

    // 1. xn = fp16(LN1(x))
    ln_kernel<<<BT, 256>>>(x, xn, ln1_g, ln1_b);
    // 2. beta_lin = xn @ in_proj_w.T  (fp32 out)
    gemm_fp16_kernel<0,false><<<dim3(1, 128), 256, SMEM_BYTES>>>(xn, w_in, beta_l, BT, 128, 1024,
                                                                 nullptr, nullptr, nullptr);
    // 3. beta = silu(causal depthwise conv + bias)
    conv_silu_kernel<<<(BT * K2) / 256, 256>>>(beta_l, conv_w, conv_b, beta_a);
    // 4. SSD -> eig (fp32 checked output) + eig_h (fp16 for GEMM)
    ssd_fused_kernel<<<Bb * NCH, 256>>>(beta_a, log_decay, frequency, coupling, eig, eig_h);
    // 5. h = eig @ out_proj_w.T
    gemm_fp16_kernel<0,false><<<dim3(8, 128), 256, SMEM_BYTES>>>(eig_h, w_out, hb, BT, 1024, 128,
                                                                 nullptr, nullptr, nullptr);
    // 6. x1 = x + sigmoid(xn @ gate_w.T + gate_b) * h
    gemm_fp16_kernel<2,false><<<dim3(8, 128), 256, SMEM_BYTES>>>(xn, w_gate, x1, BT, 1024, 1024,
                                                                 gate_b, x, hb);
    // 7. xn2 = fp16(LN2(x1))
    ln_kernel<<<BT, 256>>>(x1, xn2, ln2_g, ln2_b);
    // 8. hidden = fp16(silu(xn2 @ mlp_w1.T + b1))
    gemm_fp16_kernel<1,true><<<dim3(32, 128), 256, SMEM_BYTES>>>(xn2, w_m1, hidden, BT, 4096, 1024,
                                                                 mlp_b1, nullptr, nullptr);
    // 9. out = x1 + hidden @ mlp_w2.T + b2
    gemm_fp16_kernel<3,false><<<dim3(8, 128), 256, SMEM_BYTES>>>(hidden, w_m2, out, BT, 1024, 4096,
                                                                 mlp_b2, x1, nullptr);
}